// round 2
// baseline (speedup 1.0000x reference)
#include <cuda_runtime.h>
#include <cstdint>

#define N_NODES 100000
#define N_EDGES 3200000
#define N_GRAPHS 1024
#define HID 64

// Scratch (device globals; no allocations allowed)
__device__ float g_agg1[N_NODES * 5];
__device__ float g_h1[N_NODES * HID];
__device__ float g_agg2[N_NODES * HID];
__device__ float g_gsum[N_GRAPHS * HID];
__device__ float g_gcnt[N_GRAPHS];

// ---------------------------------------------------------------------------
// Zero all scratch buffers (grid-stride over the largest)
// ---------------------------------------------------------------------------
__global__ void zero_kernel() {
    const int total = N_NODES * HID;  // 6.4M, largest buffer
    for (int i = blockIdx.x * blockDim.x + threadIdx.x; i < total;
         i += gridDim.x * blockDim.x) {
        g_agg2[i] = 0.0f;
        if (i < N_NODES * 5) g_agg1[i] = 0.0f;
        if (i < N_GRAPHS * HID) g_gsum[i] = 0.0f;
        if (i < N_GRAPHS) g_gcnt[i] = 0.0f;
    }
}

// ---------------------------------------------------------------------------
// Graph-size counts: atomicAdd 1 per node into its graph slot
// ---------------------------------------------------------------------------
__global__ void count_kernel(const int* __restrict__ batch) {
    int i = blockIdx.x * blockDim.x + threadIdx.x;
    if (i < N_NODES) {
        atomicAdd(&g_gcnt[batch[i]], 1.0f);
    }
}

// ---------------------------------------------------------------------------
// Layer-1 aggregation: agg1[dst] += x[src], 5 features.
// One thread per (edge, feature).
// ---------------------------------------------------------------------------
__global__ void agg1_kernel(const float* __restrict__ x,
                            const int* __restrict__ ei) {
    long long tid = (long long)blockIdx.x * blockDim.x + threadIdx.x;
    if (tid >= (long long)N_EDGES * 5) return;
    int e = (int)(tid / 5);
    int j = (int)(tid % 5);
    int s = ei[e];
    int d = ei[N_EDGES + e];
    atomicAdd(&g_agg1[d * 5 + j], x[s * 5 + j]);
}

// ---------------------------------------------------------------------------
// Layer-2 aggregation: agg2[dst] += h1[src], 64 features.
// One warp per edge: 2 features per lane → coalesced 2x128B loads + adds.
// ---------------------------------------------------------------------------
__global__ void agg2_kernel(const int* __restrict__ ei) {
    long long tid = (long long)blockIdx.x * blockDim.x + threadIdx.x;
    int lane = (int)(tid & 31);
    long long e = tid >> 5;
    if (e >= N_EDGES) return;
    int s = ei[e];
    int d = ei[N_EDGES + e];
    const float* hs = g_h1 + (long long)s * HID;
    float* ad = g_agg2 + (long long)d * HID;
    atomicAdd(&ad[lane],      hs[lane]);
    atomicAdd(&ad[lane + 32], hs[lane + 32]);
}

// ---------------------------------------------------------------------------
// MLP1: h1 = relu( relu((x + agg1) @ W1a + b1a) @ W1b + b1b )
// Block: 64 x 4 threads, processes 64 nodes (16 iters of 4 rows).
// ---------------------------------------------------------------------------
__global__ __launch_bounds__(256) void mlp1_kernel(
    const float* __restrict__ x,
    const float* __restrict__ W1a, const float* __restrict__ b1a,
    const float* __restrict__ W1b, const float* __restrict__ b1b) {
    __shared__ float sWa[5 * HID];
    __shared__ float sWb[HID * HID];
    __shared__ float sba[HID];
    __shared__ float sbb[HID];
    __shared__ float sz[4][8];
    __shared__ float st[4][HID];

    int j = threadIdx.x;       // feature 0..63
    int r = threadIdx.y;       // row-in-flight 0..3
    int tid = r * 64 + j;

    for (int i = tid; i < 5 * HID; i += 256) sWa[i] = W1a[i];
    for (int i = tid; i < HID * HID; i += 256) sWb[i] = W1b[i];
    if (tid < HID) sba[tid] = b1a[tid];
    else if (tid < 2 * HID) sbb[tid - HID] = b1b[tid - HID];
    __syncthreads();

    int base = blockIdx.x * 64;
    for (int it = 0; it < 16; ++it) {
        int n = base + it * 4 + r;
        bool valid = (n < N_NODES);
        if (valid && j < 5) sz[r][j] = x[n * 5 + j] + g_agg1[n * 5 + j];
        __syncthreads();
        if (valid) {
            float acc = sba[j];
#pragma unroll
            for (int k = 0; k < 5; ++k) acc += sz[r][k] * sWa[k * HID + j];
            st[r][j] = fmaxf(acc, 0.0f);
        }
        __syncthreads();
        if (valid) {
            float acc = sbb[j];
#pragma unroll
            for (int k = 0; k < HID; ++k) acc += st[r][k] * sWb[k * HID + j];
            g_h1[(long long)n * HID + j] = fmaxf(acc, 0.0f);
        }
        __syncthreads();
    }
}

// ---------------------------------------------------------------------------
// MLP2 + fused mean-pool scatter:
// h2 = relu( relu((h1 + agg2) @ W2a + b2a) @ W2b + b2b )
// gsum[batch[n]] += h2
// ---------------------------------------------------------------------------
__global__ __launch_bounds__(256) void mlp2_kernel(
    const int* __restrict__ batch,
    const float* __restrict__ W2a, const float* __restrict__ b2a,
    const float* __restrict__ W2b, const float* __restrict__ b2b) {
    __shared__ float sWa[HID * HID];
    __shared__ float sWb[HID * HID];
    __shared__ float sba[HID];
    __shared__ float sbb[HID];
    __shared__ float sz[4][HID];
    __shared__ float st[4][HID];

    int j = threadIdx.x;
    int r = threadIdx.y;
    int tid = r * 64 + j;

    for (int i = tid; i < HID * HID; i += 256) {
        sWa[i] = W2a[i];
        sWb[i] = W2b[i];
    }
    if (tid < HID) sba[tid] = b2a[tid];
    else if (tid < 2 * HID) sbb[tid - HID] = b2b[tid - HID];
    __syncthreads();

    int base = blockIdx.x * 64;
    for (int it = 0; it < 16; ++it) {
        int n = base + it * 4 + r;
        bool valid = (n < N_NODES);
        if (valid) {
            long long off = (long long)n * HID + j;
            sz[r][j] = g_h1[off] + g_agg2[off];
        }
        __syncthreads();
        if (valid) {
            float acc = sba[j];
#pragma unroll
            for (int k = 0; k < HID; ++k) acc += sz[r][k] * sWa[k * HID + j];
            st[r][j] = fmaxf(acc, 0.0f);
        }
        __syncthreads();
        if (valid) {
            float acc = sbb[j];
#pragma unroll
            for (int k = 0; k < HID; ++k) acc += st[r][k] * sWb[k * HID + j];
            float h2 = fmaxf(acc, 0.0f);
            int g = batch[n];
            atomicAdd(&g_gsum[g * HID + j], h2);
        }
        __syncthreads();
    }
}

// ---------------------------------------------------------------------------
// Head: out[g] = (gsum[g] / max(cnt,1)) @ Wc + bc
// ---------------------------------------------------------------------------
__global__ void head_kernel(const float* __restrict__ Wc,
                            const float* __restrict__ bc,
                            float* __restrict__ out) {
    int g = blockIdx.x * blockDim.x + threadIdx.x;
    if (g >= N_GRAPHS) return;
    float inv = 1.0f / fmaxf(g_gcnt[g], 1.0f);
    float a0 = bc[0], a1 = bc[1];
#pragma unroll
    for (int jj = 0; jj < HID; ++jj) {
        float p = g_gsum[g * HID + jj] * inv;
        a0 += p * Wc[jj * 2 + 0];
        a1 += p * Wc[jj * 2 + 1];
    }
    out[g * 2 + 0] = a0;
    out[g * 2 + 1] = a1;
}

// ---------------------------------------------------------------------------
extern "C" void kernel_launch(void* const* d_in, const int* in_sizes, int n_in,
                              void* d_out, int out_size) {
    const float* x     = (const float*)d_in[0];
    const int*   ei    = (const int*)d_in[1];
    const int*   bat   = (const int*)d_in[2];
    const float* W1a = (const float*)d_in[3];
    const float* b1a = (const float*)d_in[4];
    const float* W1b = (const float*)d_in[5];
    const float* b1b = (const float*)d_in[6];
    const float* W2a = (const float*)d_in[7];
    const float* b2a = (const float*)d_in[8];
    const float* W2b = (const float*)d_in[9];
    const float* b2b = (const float*)d_in[10];
    const float* Wc  = (const float*)d_in[11];
    const float* bc  = (const float*)d_in[12];
    float* out = (float*)d_out;

    // 1. zero scratch
    zero_kernel<<<4096, 256>>>();

    // 2. counts
    count_kernel<<<(N_NODES + 255) / 256, 256>>>(bat);

    // 3. layer-1 aggregation
    {
        long long total = (long long)N_EDGES * 5;
        int blocks = (int)((total + 255) / 256);
        agg1_kernel<<<blocks, 256>>>(x, ei);
    }

    // 4. MLP1 -> h1
    mlp1_kernel<<<(N_NODES + 63) / 64, dim3(64, 4)>>>(x, W1a, b1a, W1b, b1b);

    // 5. layer-2 aggregation (warp per edge)
    {
        long long total = (long long)N_EDGES * 32;
        int blocks = (int)((total + 255) / 256);
        agg2_kernel<<<blocks, 256>>>(ei);
    }

    // 6. MLP2 + pooled sums
    mlp2_kernel<<<(N_NODES + 63) / 64, dim3(64, 4)>>>(bat, W2a, b2a, W2b, b2b);

    // 7. head
    head_kernel<<<(N_GRAPHS + 255) / 256, 256>>>(Wc, bc, out);
}

// round 3
// speedup vs baseline: 1.2696x; 1.2696x over previous
#include <cuda_runtime.h>
#include <cstdint>

#define N_NODES 100000
#define N_EDGES 3200000
#define N_GRAPHS 1024
#define HID 64

// ---------------------------------------------------------------------------
// Scratch (device globals; no allocations allowed)
// ---------------------------------------------------------------------------
__device__ int   g_deg[N_NODES];
__device__ int   g_off[N_NODES + 1];
__device__ int   g_pos[N_NODES];
__device__ int   g_srcs[N_EDGES];          // src ids grouped by dst (CSR)
__device__ float g_z1[N_NODES * 5];        // x + agg1
__device__ float g_h1[N_NODES * HID];      // layer-1 output
__device__ float g_z2[N_NODES * HID];      // h1 + agg2
__device__ float g_gsum[N_GRAPHS * HID];
__device__ float g_gcnt[N_GRAPHS];

// ---------------------------------------------------------------------------
// Zero the small scratch (deg, gsum, gcnt)
// ---------------------------------------------------------------------------
__global__ void zero_kernel() {
    int i = blockIdx.x * blockDim.x + threadIdx.x;
    if (i < N_NODES) g_deg[i] = 0;
    if (i < N_GRAPHS * HID) g_gsum[i] = 0.0f;
    if (i < N_GRAPHS) g_gcnt[i] = 0.0f;
}

// ---------------------------------------------------------------------------
// Degree histogram over dst
// ---------------------------------------------------------------------------
__global__ void hist_kernel(const int* __restrict__ ei) {
    int e = blockIdx.x * blockDim.x + threadIdx.x;
    if (e < N_EDGES) atomicAdd(&g_deg[ei[N_EDGES + e]], 1);
}

// ---------------------------------------------------------------------------
// Single-block exclusive scan of degrees -> offsets (+ fill cursors)
// ---------------------------------------------------------------------------
__global__ void scan_kernel() {
    __shared__ int ssum[1024];
    int t = threadIdx.x;
    const int CH = (N_NODES + 1023) / 1024;  // 98
    int begin = t * CH; if (begin > N_NODES) begin = N_NODES;
    int end = begin + CH; if (end > N_NODES) end = N_NODES;
    int s = 0;
    for (int i = begin; i < end; ++i) s += g_deg[i];
    ssum[t] = s;
    __syncthreads();
    // Hillis-Steele inclusive scan
    for (int d = 1; d < 1024; d <<= 1) {
        int v = (t >= d) ? ssum[t - d] : 0;
        __syncthreads();
        ssum[t] += v;
        __syncthreads();
    }
    int run = (t == 0) ? 0 : ssum[t - 1];
    for (int i = begin; i < end; ++i) {
        g_off[i] = run;
        g_pos[i] = run;
        run += g_deg[i];
    }
    if (t == 1023) g_off[N_NODES] = run;
}

// ---------------------------------------------------------------------------
// Scatter edges into CSR slots
// ---------------------------------------------------------------------------
__global__ void scatter_kernel(const int* __restrict__ ei) {
    int e = blockIdx.x * blockDim.x + threadIdx.x;
    if (e >= N_EDGES) return;
    int s = ei[e];
    int d = ei[N_EDGES + e];
    int p = atomicAdd(&g_pos[d], 1);
    g_srcs[p] = s;
}

// ---------------------------------------------------------------------------
// Graph-size counts
// ---------------------------------------------------------------------------
__global__ void count_kernel(const int* __restrict__ batch) {
    int i = blockIdx.x * blockDim.x + threadIdx.x;
    if (i < N_NODES) atomicAdd(&g_gcnt[batch[i]], 1.0f);
}

// ---------------------------------------------------------------------------
// Layer-1 gather-aggregate: z1[n] = x[n] + sum_{s in N(n)} x[s]  (5 feats)
// Warp per node; lanes stride over edges, xor-tree reduce.
// ---------------------------------------------------------------------------
__global__ void agg1_kernel(const float* __restrict__ x) {
    int gwarp = (blockIdx.x * blockDim.x + threadIdx.x) >> 5;
    int lane = threadIdx.x & 31;
    if (gwarp >= N_NODES) return;
    int start = g_off[gwarp], end = g_off[gwarp + 1];
    float a0 = 0, a1 = 0, a2 = 0, a3 = 0, a4 = 0;
    for (int e = start + lane; e < end; e += 32) {
        int s = g_srcs[e];
        const float* xs = x + s * 5;
        a0 += xs[0]; a1 += xs[1]; a2 += xs[2]; a3 += xs[3]; a4 += xs[4];
    }
#pragma unroll
    for (int off = 16; off; off >>= 1) {
        a0 += __shfl_xor_sync(0xffffffffu, a0, off);
        a1 += __shfl_xor_sync(0xffffffffu, a1, off);
        a2 += __shfl_xor_sync(0xffffffffu, a2, off);
        a3 += __shfl_xor_sync(0xffffffffu, a3, off);
        a4 += __shfl_xor_sync(0xffffffffu, a4, off);
    }
    if (lane == 0) {
        const float* xn = x + gwarp * 5;
        float* z = g_z1 + gwarp * 5;
        z[0] = xn[0] + a0; z[1] = xn[1] + a1; z[2] = xn[2] + a2;
        z[3] = xn[3] + a3; z[4] = xn[4] + a4;
    }
}

// ---------------------------------------------------------------------------
// MLP1: h1 = relu( relu(z1 @ W1a + b1a) @ W1b + b1b )
// 256 threads = 64 feats x 4 groups; 4 nodes per thread; 128 nodes per block.
// ---------------------------------------------------------------------------
#define NPB 128
__global__ __launch_bounds__(256) void mlp1_kernel(
    const float* __restrict__ W1a, const float* __restrict__ b1a,
    const float* __restrict__ W1b, const float* __restrict__ b1b) {
    __shared__ float sWa[5 * HID];
    __shared__ float sWb[HID * HID];
    __shared__ float sba[HID];
    __shared__ float sbb[HID];
    __shared__ float4 sz4[4][5];    // [r][k] -> 4 nodes
    __shared__ float4 st4[4][HID];  // [r][k] -> 4 nodes

    int j = threadIdx.x;
    int r = threadIdx.y;
    int tid = r * 64 + j;

    for (int i = tid; i < 5 * HID; i += 256) sWa[i] = W1a[i];
    for (int i = tid; i < HID * HID; i += 256) sWb[i] = W1b[i];
    if (tid < HID) sba[tid] = b1a[tid];
    else if (tid < 2 * HID) sbb[tid - HID] = b1b[tid - HID];
    __syncthreads();

    int base = blockIdx.x * NPB;
    for (int it = 0; it < NPB / 16; ++it) {
        int n0 = base + it * 16 + r * 4;
        // stage z1 for 4 nodes x 5 feats (20 threads per r-group)
        if (j < 20) {
            int i = j & 3, k = j >> 2;
            int n = n0 + i;
            float v = (n < N_NODES) ? g_z1[n * 5 + k] : 0.0f;
            ((float*)&sz4[r][k])[i] = v;
        }
        __syncthreads();
        float bias = sba[j];
        float a0 = bias, a1 = bias, a2 = bias, a3 = bias;
#pragma unroll
        for (int k = 0; k < 5; ++k) {
            float w = sWa[k * HID + j];
            float4 z = sz4[r][k];
            a0 += z.x * w; a1 += z.y * w; a2 += z.z * w; a3 += z.w * w;
        }
        float4 t;
        t.x = fmaxf(a0, 0.0f); t.y = fmaxf(a1, 0.0f);
        t.z = fmaxf(a2, 0.0f); t.w = fmaxf(a3, 0.0f);
        st4[r][j] = t;
        __syncthreads();
        float bias2 = sbb[j];
        float b0 = bias2, b1 = bias2, b2 = bias2, b3 = bias2;
#pragma unroll
        for (int k = 0; k < HID; ++k) {
            float w = sWb[k * HID + j];
            float4 z = st4[r][k];
            b0 += z.x * w; b1 += z.y * w; b2 += z.z * w; b3 += z.w * w;
        }
        if (n0 + 0 < N_NODES) g_h1[(n0 + 0) * HID + j] = fmaxf(b0, 0.0f);
        if (n0 + 1 < N_NODES) g_h1[(n0 + 1) * HID + j] = fmaxf(b1, 0.0f);
        if (n0 + 2 < N_NODES) g_h1[(n0 + 2) * HID + j] = fmaxf(b2, 0.0f);
        if (n0 + 3 < N_NODES) g_h1[(n0 + 3) * HID + j] = fmaxf(b3, 0.0f);
        __syncthreads();
    }
}

// ---------------------------------------------------------------------------
// Layer-2 gather-aggregate: z2[n] = h1[n] + sum_{s in N(n)} h1[s]  (64 feats)
// Warp per node; prefetch 32 src ids, shfl-broadcast; coalesced 2x128B loads.
// ---------------------------------------------------------------------------
__global__ void agg2_kernel() {
    int gwarp = (blockIdx.x * blockDim.x + threadIdx.x) >> 5;
    int lane = threadIdx.x & 31;
    if (gwarp >= N_NODES) return;
    int start = g_off[gwarp], end = g_off[gwarp + 1];
    float a0 = 0.0f, a1 = 0.0f;
    for (int b = start; b < end; b += 32) {
        int m = end - b; if (m > 32) m = 32;
        int myS = (b + lane < end) ? g_srcs[b + lane] : 0;
        for (int i = 0; i < m; ++i) {
            int s = __shfl_sync(0xffffffffu, myS, i);
            const float* hs = g_h1 + (long long)s * HID;
            a0 += hs[lane];
            a1 += hs[lane + 32];
        }
    }
    const float* hn = g_h1 + (long long)gwarp * HID;
    float* z = g_z2 + (long long)gwarp * HID;
    z[lane] = hn[lane] + a0;
    z[lane + 32] = hn[lane + 32] + a1;
}

// ---------------------------------------------------------------------------
// MLP2 + fused mean-pool scatter:
// h2 = relu( relu(z2 @ W2a + b2a) @ W2b + b2b );  gsum[batch[n]] += h2
// ---------------------------------------------------------------------------
__global__ __launch_bounds__(256) void mlp2_kernel(
    const int* __restrict__ batch,
    const float* __restrict__ W2a, const float* __restrict__ b2a,
    const float* __restrict__ W2b, const float* __restrict__ b2b) {
    __shared__ float sWa[HID * HID];
    __shared__ float sWb[HID * HID];
    __shared__ float sba[HID];
    __shared__ float sbb[HID];
    __shared__ float4 sz4[4][HID];  // [r][k] -> 4 nodes
    __shared__ float4 st4[4][HID];

    int j = threadIdx.x;
    int r = threadIdx.y;
    int tid = r * 64 + j;

    for (int i = tid; i < HID * HID; i += 256) {
        sWa[i] = W2a[i];
        sWb[i] = W2b[i];
    }
    if (tid < HID) sba[tid] = b2a[tid];
    else if (tid < 2 * HID) sbb[tid - HID] = b2b[tid - HID];
    __syncthreads();

    int base = blockIdx.x * NPB;
    for (int it = 0; it < NPB / 16; ++it) {
        int n0 = base + it * 16 + r * 4;
        // stage z2 transposed: sz4[r][j] = {z2[n0..n0+3][j]}
        {
            float4 v;
            v.x = (n0 + 0 < N_NODES) ? g_z2[(n0 + 0) * HID + j] : 0.0f;
            v.y = (n0 + 1 < N_NODES) ? g_z2[(n0 + 1) * HID + j] : 0.0f;
            v.z = (n0 + 2 < N_NODES) ? g_z2[(n0 + 2) * HID + j] : 0.0f;
            v.w = (n0 + 3 < N_NODES) ? g_z2[(n0 + 3) * HID + j] : 0.0f;
            sz4[r][j] = v;
        }
        __syncthreads();
        float bias = sba[j];
        float a0 = bias, a1 = bias, a2 = bias, a3 = bias;
#pragma unroll
        for (int k = 0; k < HID; ++k) {
            float w = sWa[k * HID + j];
            float4 z = sz4[r][k];
            a0 += z.x * w; a1 += z.y * w; a2 += z.z * w; a3 += z.w * w;
        }
        float4 t;
        t.x = fmaxf(a0, 0.0f); t.y = fmaxf(a1, 0.0f);
        t.z = fmaxf(a2, 0.0f); t.w = fmaxf(a3, 0.0f);
        st4[r][j] = t;
        __syncthreads();
        float bias2 = sbb[j];
        float b0 = bias2, b1 = bias2, b2 = bias2, b3 = bias2;
#pragma unroll
        for (int k = 0; k < HID; ++k) {
            float w = sWb[k * HID + j];
            float4 z = st4[r][k];
            b0 += z.x * w; b1 += z.y * w; b2 += z.z * w; b3 += z.w * w;
        }
        if (n0 + 0 < N_NODES) atomicAdd(&g_gsum[batch[n0 + 0] * HID + j], fmaxf(b0, 0.0f));
        if (n0 + 1 < N_NODES) atomicAdd(&g_gsum[batch[n0 + 1] * HID + j], fmaxf(b1, 0.0f));
        if (n0 + 2 < N_NODES) atomicAdd(&g_gsum[batch[n0 + 2] * HID + j], fmaxf(b2, 0.0f));
        if (n0 + 3 < N_NODES) atomicAdd(&g_gsum[batch[n0 + 3] * HID + j], fmaxf(b3, 0.0f));
        __syncthreads();
    }
}

// ---------------------------------------------------------------------------
// Head: out[g] = (gsum[g] / max(cnt,1)) @ Wc + bc
// ---------------------------------------------------------------------------
__global__ void head_kernel(const float* __restrict__ Wc,
                            const float* __restrict__ bc,
                            float* __restrict__ out) {
    int g = blockIdx.x * blockDim.x + threadIdx.x;
    if (g >= N_GRAPHS) return;
    float inv = 1.0f / fmaxf(g_gcnt[g], 1.0f);
    float a0 = bc[0], a1 = bc[1];
#pragma unroll
    for (int jj = 0; jj < HID; ++jj) {
        float p = g_gsum[g * HID + jj] * inv;
        a0 += p * Wc[jj * 2 + 0];
        a1 += p * Wc[jj * 2 + 1];
    }
    out[g * 2 + 0] = a0;
    out[g * 2 + 1] = a1;
}

// ---------------------------------------------------------------------------
extern "C" void kernel_launch(void* const* d_in, const int* in_sizes, int n_in,
                              void* d_out, int out_size) {
    const float* x   = (const float*)d_in[0];
    const int*   ei  = (const int*)d_in[1];
    const int*   bat = (const int*)d_in[2];
    const float* W1a = (const float*)d_in[3];
    const float* b1a = (const float*)d_in[4];
    const float* W1b = (const float*)d_in[5];
    const float* b1b = (const float*)d_in[6];
    const float* W2a = (const float*)d_in[7];
    const float* b2a = (const float*)d_in[8];
    const float* W2b = (const float*)d_in[9];
    const float* b2b = (const float*)d_in[10];
    const float* Wc  = (const float*)d_in[11];
    const float* bc  = (const float*)d_in[12];
    float* out = (float*)d_out;

    zero_kernel<<<(N_NODES + 255) / 256, 256>>>();
    hist_kernel<<<(N_EDGES + 255) / 256, 256>>>(ei);
    scan_kernel<<<1, 1024>>>();
    scatter_kernel<<<(N_EDGES + 255) / 256, 256>>>(ei);
    count_kernel<<<(N_NODES + 255) / 256, 256>>>(bat);

    // layer 1
    agg1_kernel<<<(N_NODES * 32 + 255) / 256, 256>>>(x);
    mlp1_kernel<<<(N_NODES + NPB - 1) / NPB, dim3(64, 4)>>>(W1a, b1a, W1b, b1b);

    // layer 2
    agg2_kernel<<<(N_NODES * 32 + 255) / 256, 256>>>();
    mlp2_kernel<<<(N_NODES + NPB - 1) / NPB, dim3(64, 4)>>>(bat, W2a, b2a, W2b, b2b);

    head_kernel<<<(N_GRAPHS + 255) / 256, 256>>>(Wc, bc, out);
}

// round 4
// speedup vs baseline: 1.5540x; 1.2240x over previous
#include <cuda_runtime.h>
#include <cuda_fp16.h>
#include <cstdint>

#define N_NODES 100000
#define N_EDGES 3200000
#define N_GRAPHS 1024
#define HID 64

// ---------------------------------------------------------------------------
// Scratch (device globals; no allocations allowed)
// ---------------------------------------------------------------------------
__device__ int     g_deg[N_NODES];
__device__ int     g_off[N_NODES + 1];
__device__ int     g_rank[N_EDGES];          // per-edge rank within its dst bucket
__device__ int     g_srcs[N_EDGES];          // src ids grouped by dst (CSR)
__device__ float   g_z1[N_NODES * 5];        // x + agg1
__device__ __half2 g_h1h[N_NODES * (HID/2)]; // layer-1 output (fp16)
__device__ float   g_z2[N_NODES * HID];      // h1 + agg2 (fp32)
__device__ float   g_gsum[N_GRAPHS * HID];
__device__ float   g_gcnt[N_GRAPHS];

// ---------------------------------------------------------------------------
// Zero the small scratch (deg, gsum, gcnt)
// ---------------------------------------------------------------------------
__global__ void zero_kernel() {
    int i = blockIdx.x * blockDim.x + threadIdx.x;
    if (i < N_NODES) g_deg[i] = 0;
    if (i < N_GRAPHS * HID) g_gsum[i] = 0.0f;
    if (i < N_GRAPHS) g_gcnt[i] = 0.0f;
}

// ---------------------------------------------------------------------------
// Degree histogram over dst; the atomic's return value is the edge's rank.
// ---------------------------------------------------------------------------
__global__ void hist_kernel(const int* __restrict__ ei) {
    int e = blockIdx.x * blockDim.x + threadIdx.x;
    if (e < N_EDGES) {
        int d = ei[N_EDGES + e];
        g_rank[e] = atomicAdd(&g_deg[d], 1);
    }
}

// ---------------------------------------------------------------------------
// Single-block exclusive scan of degrees -> offsets
// ---------------------------------------------------------------------------
__global__ void scan_kernel() {
    __shared__ int ssum[1024];
    int t = threadIdx.x;
    const int CH = (N_NODES + 1023) / 1024;  // 98
    int begin = t * CH; if (begin > N_NODES) begin = N_NODES;
    int end = begin + CH; if (end > N_NODES) end = N_NODES;
    int s = 0;
    for (int i = begin; i < end; ++i) s += g_deg[i];
    ssum[t] = s;
    __syncthreads();
    for (int d = 1; d < 1024; d <<= 1) {
        int v = (t >= d) ? ssum[t - d] : 0;
        __syncthreads();
        ssum[t] += v;
        __syncthreads();
    }
    int run = (t == 0) ? 0 : ssum[t - 1];
    for (int i = begin; i < end; ++i) {
        g_off[i] = run;
        run += g_deg[i];
    }
    if (t == 1023) g_off[N_NODES] = run;
}

// ---------------------------------------------------------------------------
// Scatter edges into CSR slots (no atomics: rank precomputed in hist)
// ---------------------------------------------------------------------------
__global__ void scatter_kernel(const int* __restrict__ ei) {
    int e = blockIdx.x * blockDim.x + threadIdx.x;
    if (e >= N_EDGES) return;
    int s = ei[e];
    int d = ei[N_EDGES + e];
    g_srcs[g_off[d] + g_rank[e]] = s;
}

// ---------------------------------------------------------------------------
// Graph-size counts
// ---------------------------------------------------------------------------
__global__ void count_kernel(const int* __restrict__ batch) {
    int i = blockIdx.x * blockDim.x + threadIdx.x;
    if (i < N_NODES) atomicAdd(&g_gcnt[batch[i]], 1.0f);
}

// ---------------------------------------------------------------------------
// Layer-1 gather-aggregate: z1[n] = x[n] + sum_{s in N(n)} x[s]  (5 feats)
// ---------------------------------------------------------------------------
__global__ void agg1_kernel(const float* __restrict__ x) {
    int gwarp = (blockIdx.x * blockDim.x + threadIdx.x) >> 5;
    int lane = threadIdx.x & 31;
    if (gwarp >= N_NODES) return;
    int start = g_off[gwarp], end = g_off[gwarp + 1];
    float a0 = 0, a1 = 0, a2 = 0, a3 = 0, a4 = 0;
    for (int e = start + lane; e < end; e += 32) {
        int s = g_srcs[e];
        const float* xs = x + s * 5;
        a0 += xs[0]; a1 += xs[1]; a2 += xs[2]; a3 += xs[3]; a4 += xs[4];
    }
#pragma unroll
    for (int off = 16; off; off >>= 1) {
        a0 += __shfl_xor_sync(0xffffffffu, a0, off);
        a1 += __shfl_xor_sync(0xffffffffu, a1, off);
        a2 += __shfl_xor_sync(0xffffffffu, a2, off);
        a3 += __shfl_xor_sync(0xffffffffu, a3, off);
        a4 += __shfl_xor_sync(0xffffffffu, a4, off);
    }
    if (lane == 0) {
        const float* xn = x + gwarp * 5;
        float* z = g_z1 + gwarp * 5;
        z[0] = xn[0] + a0; z[1] = xn[1] + a1; z[2] = xn[2] + a2;
        z[3] = xn[3] + a3; z[4] = xn[4] + a4;
    }
}

// ---------------------------------------------------------------------------
// MLP1: h1 = relu( relu(z1 @ W1a + b1a) @ W1b + b1b ), output fp16.
// 256 threads = 64 feats x 4 groups; 8 nodes/thread; 128 nodes/block.
// ---------------------------------------------------------------------------
#define NPB 128
__global__ __launch_bounds__(256) void mlp1_kernel(
    const float* __restrict__ W1a, const float* __restrict__ b1a,
    const float* __restrict__ W1b, const float* __restrict__ b1b) {
    __shared__ float sWa[5 * HID];
    __shared__ float sWb[HID * HID];
    __shared__ float sba[HID];
    __shared__ float sbb[HID];
    __shared__ float sz[4][5][8];    // [r][k][node8]
    __shared__ float st[4][HID][8];  // [r][k][node8]

    int j = threadIdx.x;
    int r = threadIdx.y;
    int tid = r * 64 + j;

    for (int i = tid; i < 5 * HID; i += 256) sWa[i] = W1a[i];
    for (int i = tid; i < HID * HID; i += 256) sWb[i] = W1b[i];
    if (tid < HID) sba[tid] = b1a[tid];
    else if (tid < 2 * HID) sbb[tid - HID] = b1b[tid - HID];
    __syncthreads();

    int base = blockIdx.x * NPB;
    for (int it = 0; it < NPB / 32; ++it) {
        int n0 = base + it * 32 + r * 8;
        // stage z1 for 8 nodes x 5 feats (40 threads per r-group)
        if (j < 40) {
            int i = j & 7, k = j >> 3;
            int n = n0 + i;
            sz[r][k][i] = (n < N_NODES) ? g_z1[n * 5 + k] : 0.0f;
        }
        __syncthreads();
        float bias = sba[j];
        float a0 = bias, a1 = bias, a2 = bias, a3 = bias;
        float a4 = bias, a5 = bias, a6 = bias, a7 = bias;
#pragma unroll
        for (int k = 0; k < 5; ++k) {
            float w = sWa[k * HID + j];
            float4 za = *(const float4*)&sz[r][k][0];
            float4 zb = *(const float4*)&sz[r][k][4];
            a0 += za.x * w; a1 += za.y * w; a2 += za.z * w; a3 += za.w * w;
            a4 += zb.x * w; a5 += zb.y * w; a6 += zb.z * w; a7 += zb.w * w;
        }
        float4 ta, tb;
        ta.x = fmaxf(a0, 0.0f); ta.y = fmaxf(a1, 0.0f);
        ta.z = fmaxf(a2, 0.0f); ta.w = fmaxf(a3, 0.0f);
        tb.x = fmaxf(a4, 0.0f); tb.y = fmaxf(a5, 0.0f);
        tb.z = fmaxf(a6, 0.0f); tb.w = fmaxf(a7, 0.0f);
        *(float4*)&st[r][j][0] = ta;
        *(float4*)&st[r][j][4] = tb;
        __syncthreads();
        float bias2 = sbb[j];
        float b0 = bias2, b1 = bias2, b2 = bias2, b3 = bias2;
        float b4 = bias2, b5 = bias2, b6 = bias2, b7 = bias2;
#pragma unroll
        for (int k = 0; k < HID; ++k) {
            float w = sWb[k * HID + j];
            float4 za = *(const float4*)&st[r][k][0];
            float4 zb = *(const float4*)&st[r][k][4];
            b0 += za.x * w; b1 += za.y * w; b2 += za.z * w; b3 += za.w * w;
            b4 += zb.x * w; b5 += zb.y * w; b6 += zb.z * w; b7 += zb.w * w;
        }
        __half* h1 = (__half*)g_h1h;
        if (n0 + 0 < N_NODES) h1[(n0 + 0) * HID + j] = __float2half(fmaxf(b0, 0.0f));
        if (n0 + 1 < N_NODES) h1[(n0 + 1) * HID + j] = __float2half(fmaxf(b1, 0.0f));
        if (n0 + 2 < N_NODES) h1[(n0 + 2) * HID + j] = __float2half(fmaxf(b2, 0.0f));
        if (n0 + 3 < N_NODES) h1[(n0 + 3) * HID + j] = __float2half(fmaxf(b3, 0.0f));
        if (n0 + 4 < N_NODES) h1[(n0 + 4) * HID + j] = __float2half(fmaxf(b4, 0.0f));
        if (n0 + 5 < N_NODES) h1[(n0 + 5) * HID + j] = __float2half(fmaxf(b5, 0.0f));
        if (n0 + 6 < N_NODES) h1[(n0 + 6) * HID + j] = __float2half(fmaxf(b6, 0.0f));
        if (n0 + 7 < N_NODES) h1[(n0 + 7) * HID + j] = __float2half(fmaxf(b7, 0.0f));
        __syncthreads();
    }
}

// ---------------------------------------------------------------------------
// Layer-2 gather-aggregate (fp16 gather, fp32 accumulate):
// z2[n] = h1[n] + sum_{s in N(n)} h1[s]
// Warp per node; each lane owns one half2 (2 feats); 1x128B load per edge.
// ---------------------------------------------------------------------------
__global__ void agg2_kernel() {
    int gwarp = (blockIdx.x * blockDim.x + threadIdx.x) >> 5;
    int lane = threadIdx.x & 31;
    if (gwarp >= N_NODES) return;
    int start = g_off[gwarp], end = g_off[gwarp + 1];
    float a0 = 0.0f, a1 = 0.0f;
    for (int b = start; b < end; b += 32) {
        int m = end - b; if (m > 32) m = 32;
        int myS = (b + lane < end) ? g_srcs[b + lane] : 0;
        for (int i = 0; i < m; ++i) {
            int s = __shfl_sync(0xffffffffu, myS, i);
            __half2 v = g_h1h[s * (HID/2) + lane];
            float2 f = __half22float2(v);
            a0 += f.x;
            a1 += f.y;
        }
    }
    float2 hs = __half22float2(g_h1h[gwarp * (HID/2) + lane]);
    float2 z;
    z.x = hs.x + a0;
    z.y = hs.y + a1;
    ((float2*)g_z2)[gwarp * (HID/2) + lane] = z;
}

// ---------------------------------------------------------------------------
// MLP2 + fused mean-pool scatter:
// h2 = relu( relu(z2 @ W2a + b2a) @ W2b + b2b );  gsum[batch[n]] += h2
// ---------------------------------------------------------------------------
__global__ __launch_bounds__(256) void mlp2_kernel(
    const int* __restrict__ batch,
    const float* __restrict__ W2a, const float* __restrict__ b2a,
    const float* __restrict__ W2b, const float* __restrict__ b2b) {
    __shared__ float sWa[HID * HID];
    __shared__ float sWb[HID * HID];
    __shared__ float sba[HID];
    __shared__ float sbb[HID];
    __shared__ float sz[4][HID][8];
    __shared__ float st[4][HID][8];

    int j = threadIdx.x;
    int r = threadIdx.y;
    int tid = r * 64 + j;

    for (int i = tid; i < HID * HID; i += 256) {
        sWa[i] = W2a[i];
        sWb[i] = W2b[i];
    }
    if (tid < HID) sba[tid] = b2a[tid];
    else if (tid < 2 * HID) sbb[tid - HID] = b2b[tid - HID];
    __syncthreads();

    int base = blockIdx.x * NPB;
    for (int it = 0; it < NPB / 32; ++it) {
        int n0 = base + it * 32 + r * 8;
        // stage z2 transposed: sz[r][j][i] = z2[n0+i][j]
#pragma unroll
        for (int i = 0; i < 8; ++i) {
            int n = n0 + i;
            sz[r][j][i] = (n < N_NODES) ? g_z2[n * HID + j] : 0.0f;
        }
        __syncthreads();
        float bias = sba[j];
        float a0 = bias, a1 = bias, a2 = bias, a3 = bias;
        float a4 = bias, a5 = bias, a6 = bias, a7 = bias;
#pragma unroll
        for (int k = 0; k < HID; ++k) {
            float w = sWa[k * HID + j];
            float4 za = *(const float4*)&sz[r][k][0];
            float4 zb = *(const float4*)&sz[r][k][4];
            a0 += za.x * w; a1 += za.y * w; a2 += za.z * w; a3 += za.w * w;
            a4 += zb.x * w; a5 += zb.y * w; a6 += zb.z * w; a7 += zb.w * w;
        }
        float4 ta, tb;
        ta.x = fmaxf(a0, 0.0f); ta.y = fmaxf(a1, 0.0f);
        ta.z = fmaxf(a2, 0.0f); ta.w = fmaxf(a3, 0.0f);
        tb.x = fmaxf(a4, 0.0f); tb.y = fmaxf(a5, 0.0f);
        tb.z = fmaxf(a6, 0.0f); tb.w = fmaxf(a7, 0.0f);
        *(float4*)&st[r][j][0] = ta;
        *(float4*)&st[r][j][4] = tb;
        __syncthreads();
        float bias2 = sbb[j];
        float b0 = bias2, b1 = bias2, b2 = bias2, b3 = bias2;
        float b4 = bias2, b5 = bias2, b6 = bias2, b7 = bias2;
#pragma unroll
        for (int k = 0; k < HID; ++k) {
            float w = sWb[k * HID + j];
            float4 za = *(const float4*)&st[r][k][0];
            float4 zb = *(const float4*)&st[r][k][4];
            b0 += za.x * w; b1 += za.y * w; b2 += za.z * w; b3 += za.w * w;
            b4 += zb.x * w; b5 += zb.y * w; b6 += zb.z * w; b7 += zb.w * w;
        }
        if (n0 + 0 < N_NODES) atomicAdd(&g_gsum[batch[n0 + 0] * HID + j], fmaxf(b0, 0.0f));
        if (n0 + 1 < N_NODES) atomicAdd(&g_gsum[batch[n0 + 1] * HID + j], fmaxf(b1, 0.0f));
        if (n0 + 2 < N_NODES) atomicAdd(&g_gsum[batch[n0 + 2] * HID + j], fmaxf(b2, 0.0f));
        if (n0 + 3 < N_NODES) atomicAdd(&g_gsum[batch[n0 + 3] * HID + j], fmaxf(b3, 0.0f));
        if (n0 + 4 < N_NODES) atomicAdd(&g_gsum[batch[n0 + 4] * HID + j], fmaxf(b4, 0.0f));
        if (n0 + 5 < N_NODES) atomicAdd(&g_gsum[batch[n0 + 5] * HID + j], fmaxf(b5, 0.0f));
        if (n0 + 6 < N_NODES) atomicAdd(&g_gsum[batch[n0 + 6] * HID + j], fmaxf(b6, 0.0f));
        if (n0 + 7 < N_NODES) atomicAdd(&g_gsum[batch[n0 + 7] * HID + j], fmaxf(b7, 0.0f));
        __syncthreads();
    }
}

// ---------------------------------------------------------------------------
// Head: out[g] = (gsum[g] / max(cnt,1)) @ Wc + bc
// ---------------------------------------------------------------------------
__global__ void head_kernel(const float* __restrict__ Wc,
                            const float* __restrict__ bc,
                            float* __restrict__ out) {
    int g = blockIdx.x * blockDim.x + threadIdx.x;
    if (g >= N_GRAPHS) return;
    float inv = 1.0f / fmaxf(g_gcnt[g], 1.0f);
    float a0 = bc[0], a1 = bc[1];
#pragma unroll
    for (int jj = 0; jj < HID; ++jj) {
        float p = g_gsum[g * HID + jj] * inv;
        a0 += p * Wc[jj * 2 + 0];
        a1 += p * Wc[jj * 2 + 1];
    }
    out[g * 2 + 0] = a0;
    out[g * 2 + 1] = a1;
}

// ---------------------------------------------------------------------------
extern "C" void kernel_launch(void* const* d_in, const int* in_sizes, int n_in,
                              void* d_out, int out_size) {
    const float* x   = (const float*)d_in[0];
    const int*   ei  = (const int*)d_in[1];
    const int*   bat = (const int*)d_in[2];
    const float* W1a = (const float*)d_in[3];
    const float* b1a = (const float*)d_in[4];
    const float* W1b = (const float*)d_in[5];
    const float* b1b = (const float*)d_in[6];
    const float* W2a = (const float*)d_in[7];
    const float* b2a = (const float*)d_in[8];
    const float* W2b = (const float*)d_in[9];
    const float* b2b = (const float*)d_in[10];
    const float* Wc  = (const float*)d_in[11];
    const float* bc  = (const float*)d_in[12];
    float* out = (float*)d_out;

    zero_kernel<<<(N_NODES + 255) / 256, 256>>>();
    hist_kernel<<<(N_EDGES + 255) / 256, 256>>>(ei);
    scan_kernel<<<1, 1024>>>();
    scatter_kernel<<<(N_EDGES + 255) / 256, 256>>>(ei);
    count_kernel<<<(N_NODES + 255) / 256, 256>>>(bat);

    // layer 1
    agg1_kernel<<<(N_NODES * 32 + 255) / 256, 256>>>(x);
    mlp1_kernel<<<(N_NODES + NPB - 1) / NPB, dim3(64, 4)>>>(W1a, b1a, W1b, b1b);

    // layer 2
    agg2_kernel<<<(N_NODES * 32 + 255) / 256, 256>>>();
    mlp2_kernel<<<(N_NODES + NPB - 1) / NPB, dim3(64, 4)>>>(bat, W2a, b2a, W2b, b2b);

    head_kernel<<<(N_GRAPHS + 255) / 256, 256>>>(Wc, bc, out);
}